// round 9
// baseline (speedup 1.0000x reference)
#include <cuda_runtime.h>
#include <cuda_fp16.h>
#include <cstdint>
#include <cstddef>

#define T_STEPS 512
#define DH      2048
#define DI      64
#define DO      64
#define BATCH   128
#define HC      64
#define NCHUNK  (DH / HC)        // 32
#define NB      64               // batch cols per block
#define USTR    72               // u32 stride (conflict-free: 72 mod 32 = 8)

// ---- device scratch ----
__device__ float    g_base[DH * BATCH];            // 1 MB
__device__ float    g_part[4 * DH * BATCH];        // 4 MB K-quarter partials
__device__ unsigned g_win_h[NCHUNK * 2048];        // fp16x2 win A-fragments
__device__ unsigned g_wout_h[NCHUNK * 2048];       // fp16x2 wout A-fragments (K-permuted)
__device__ unsigned g_wfrag[4 * 32 * 32 * 4 * 32 * 4]; // |w| fp16 A-frags, 8 MB
__device__ unsigned g_spk[1024 * 128];             // sigmoid(r0) fp16 k-pair

// ---------- helpers ----------
__device__ __forceinline__ float sigm_exact(float x) {
    return __fdividef(1.0f, 1.0f + __expf(-x));
}
__device__ __forceinline__ float sigm(float x) {
    float t;
    asm("tanh.approx.f32 %0, %1;" : "=f"(t) : "f"(0.5f * x));
    return fmaf(0.5f, t, 0.5f);
}
__device__ __forceinline__ unsigned packh2(float a, float b) {
    __half2 h = __floats2half2_rn(a, b);   // a -> low half
    return *(unsigned*)&h;
}
__device__ __forceinline__ void mma_f16(float& c0, float& c1, float& c2, float& c3,
                                        unsigned a0, unsigned a1, unsigned a2, unsigned a3,
                                        unsigned b0, unsigned b1) {
    asm volatile("mma.sync.aligned.m16n8k16.row.col.f32.f16.f16.f32 "
                 "{%0,%1,%2,%3}, {%4,%5,%6,%7}, {%8,%9}, {%0,%1,%2,%3};"
                 : "+f"(c0), "+f"(c1), "+f"(c2), "+f"(c3)
                 : "r"(a0), "r"(a1), "r"(a2), "r"(a3), "r"(b0), "r"(b1));
}

// ---------- kernel 1: all packing (win, wout, |w|, sigmoid(r0)) ----------
__global__ void pack_all_kernel(const float* __restrict__ win,
                                const float* __restrict__ wout,
                                const float* __restrict__ r0,
                                const float* __restrict__ w_) {
    int bx = blockIdx.x;
    int tid = threadIdx.x;
    if (bx < 128) {
        int tg = (bx & 63) * 256 + tid;       // 0..16383
        int lane = tg & 31;
        int mt = (tg >> 5) & 3;
        int kt = (tg >> 7) & 3;
        int c  = tg >> 9;
        uint4 oh;
        if (bx < 64) {
            // win: natural K order
            int r = (c * 4 + mt) * 16 + (lane >> 2);
            int k0 = kt * 16 + 2 * (lane & 3);
            oh.x = packh2(win[r * DI + k0],           win[r * DI + k0 + 1]);
            oh.y = packh2(win[(r + 8) * DI + k0],     win[(r + 8) * DI + k0 + 1]);
            oh.z = packh2(win[r * DI + k0 + 8],       win[r * DI + k0 + 9]);
            oh.w = packh2(win[(r + 8) * DI + k0 + 8], win[(r + 8) * DI + k0 + 9]);
            *(uint4*)(g_win_h + (size_t)tg * 4) = oh;
        } else {
            // wout: permuted K so that pair (2p,2p+1) <-> h = (Hp, Hp+8)
            // k = kt*16 + 2*q3 -> h0 = kt*16 + q3;  k+8 -> h2 = kt*16 + 4 + q3
            int r = mt * 16 + (lane >> 2);
            int q3 = lane & 3;
            int h0 = c * HC + kt * 16 + q3;       // pair low  (e=0), high = h0+8
            int h2 = h0 + 4;                      // k+8 pair
            oh.x = packh2(wout[r * DH + h0],           wout[r * DH + h0 + 8]);
            oh.y = packh2(wout[(r + 8) * DH + h0],     wout[(r + 8) * DH + h0 + 8]);
            oh.z = packh2(wout[r * DH + h2],           wout[r * DH + h2 + 8]);
            oh.w = packh2(wout[(r + 8) * DH + h2],     wout[(r + 8) * DH + h2 + 8]);
            *(uint4*)(g_wout_h + (size_t)tg * 4) = oh;
        }
    } else if (bx < 384) {
        int i = (bx - 128) * 256 + tid;       // 0..65535
        int bp = i & 63;
        int kp = i >> 6;                       // 0..1023
        float2 ra = *(const float2*)(r0 + (size_t)(2 * kp) * BATCH + 2 * bp);
        float2 rb = *(const float2*)(r0 + (size_t)(2 * kp + 1) * BATCH + 2 * bp);
        uint2 o;
        o.x = packh2(sigm_exact(ra.x), sigm_exact(rb.x));
        o.y = packh2(sigm_exact(ra.y), sigm_exact(rb.y));
        *(uint2*)(g_spk + (size_t)kp * BATCH + 2 * bp) = o;
    } else {
        int tg = (bx - 384) * 256 + tid;      // 0..524287
        int lane = tg & 31;
        int mt = (tg >> 5) & 3;
        int kt = (tg >> 7) & 31;
        int hc = (tg >> 12) & 31;
        int kq = tg >> 17;
        int r  = hc * HC + mt * 16 + (lane >> 2);
        int k0 = kq * 512 + kt * 16 + 2 * (lane & 3);
        uint4 oh;
        oh.x = packh2(fabsf(w_[(size_t)r * DH + k0]),
                      fabsf(w_[(size_t)r * DH + k0 + 1]));
        oh.y = packh2(fabsf(w_[(size_t)(r + 8) * DH + k0]),
                      fabsf(w_[(size_t)(r + 8) * DH + k0 + 1]));
        oh.z = packh2(fabsf(w_[(size_t)r * DH + k0 + 8]),
                      fabsf(w_[(size_t)r * DH + k0 + 9]));
        oh.w = packh2(fabsf(w_[(size_t)(r + 8) * DH + k0 + 8]),
                      fabsf(w_[(size_t)(r + 8) * DH + k0 + 9]));
        *(uint4*)(g_wfrag + (size_t)tg * 4) = oh;
    }
}

// ---------- kernel 2: base GEMM partials ----------
__global__ void __launch_bounds__(256)
base_gemm_kernel() {
    int bx = blockIdx.x;
    int kq = bx >> 6;
    int hc = (bx >> 1) & 31;
    int nh = bx & 1;

    int tid  = threadIdx.x;
    int lane = tid & 31;
    int w    = tid >> 5;
    int qq   = lane & 3;
    int rr   = lane >> 2;
    int n    = nh * NB + w * 8 + rr;

    float C[4][4];
#pragma unroll
    for (int a = 0; a < 4; ++a)
#pragma unroll
        for (int q = 0; q < 4; ++q) C[a][q] = 0.0f;

    const uint4* Af = ((const uint4*)g_wfrag) + ((size_t)(kq * 32 + hc) * 32) * 128;

#pragma unroll 4
    for (int kt = 0; kt < 32; ++kt) {
        int kp = kq * 256 + kt * 8;
        unsigned b0 = g_spk[(size_t)(kp + qq) * BATCH + n];
        unsigned b1 = g_spk[(size_t)(kp + 4 + qq) * BATCH + n];
#pragma unroll
        for (int mt = 0; mt < 4; ++mt) {
            uint4 a4 = Af[(kt * 4 + mt) * 32 + lane];
            mma_f16(C[mt][0], C[mt][1], C[mt][2], C[mt][3],
                    a4.x, a4.y, a4.z, a4.w, b0, b1);
        }
    }

    float* dst = g_part + (size_t)kq * DH * BATCH;
    int n0 = nh * NB + w * 8 + 2 * qq;
#pragma unroll
    for (int mt = 0; mt < 4; ++mt)
#pragma unroll
        for (int hh = 0; hh < 2; ++hh) {
            int h = hc * HC + mt * 16 + hh * 8 + rr;
            *(float2*)(dst + (size_t)h * BATCH + n0) =
                make_float2(C[mt][hh * 2], C[mt][hh * 2 + 1]);
        }
}

// ---------- kernel 3: base = (1-a)*r0 + a*(p0+p1+p2+p3) ----------
__global__ void base_reduce_kernel(const float* __restrict__ r0,
                                   const float* __restrict__ taus) {
    int i4 = (blockIdx.x * blockDim.x + threadIdx.x) * 4;
    int h  = i4 >> 7;
    float alpha = 1.0f / taus[h];
    float om = 1.0f - alpha;
    float4 rv = *(const float4*)(r0 + i4);
    float4 p0 = *(const float4*)(g_part + i4);
    float4 p1 = *(const float4*)(g_part + DH * BATCH + i4);
    float4 p2 = *(const float4*)(g_part + 2 * DH * BATCH + i4);
    float4 p3 = *(const float4*)(g_part + 3 * DH * BATCH + i4);
    float4 o;
    o.x = om * rv.x + alpha * (p0.x + p1.x + p2.x + p3.x);
    o.y = om * rv.y + alpha * (p0.y + p1.y + p2.y + p3.y);
    o.z = om * rv.z + alpha * (p0.z + p1.z + p2.z + p3.z);
    o.w = om * rv.w + alpha * (p0.w + p1.w + p2.w + p3.w);
    *(float4*)(g_base + i4) = o;
}

// ---------- kernel 4: main, 2 timesteps per block ----------
// smem (u32): WINB[2] 0..4096 | WOUTB[2] 4096..8192 |
//   UH0 8192..10496 | UH1 10496..12800 |
//   S0[2] 12800..17408 | S1[2] 17408..22016   (2304 each, stride 72, 32 rows)
#define OFF_WOUT 4096
#define OFF_UH0  8192
#define OFF_UH1  10496
#define OFF_S0   12800
#define OFF_S1   17408
#define SMEM_U32 22016

__global__ void __launch_bounds__(256, 2)
main_kernel(const float* __restrict__ u,
            const float* __restrict__ noise,
            const float* __restrict__ bias,
            float* __restrict__ out) {
    extern __shared__ unsigned smu[];
    unsigned* WINB  = smu;
    unsigned* WOUTB = smu + OFF_WOUT;

    int tid  = threadIdx.x;
    int lane = tid & 31;
    int w    = tid >> 5;
    int qq   = lane & 3;
    int rr   = lane >> 2;

    int t0 = (blockIdx.x >> 1) * 2;
    int t1 = t0 + 1;
    int nb = (blockIdx.x & 1) * NB;

    float* xsout = out + (size_t)T_STEPS * DO * BATCH;

    // ---- prologue: stage u[t0], u[t1] (fp16 hi only, k-pair interleave) ----
#pragma unroll
    for (int tt = 0; tt < 2; ++tt) {
        const float* ut = u + (size_t)(t0 + tt) * DI * BATCH + nb;
        unsigned* uh = smu + (tt ? OFF_UH1 : OFF_UH0);
#pragma unroll
        for (int i = 0; i < 4; ++i) {
            int idx = tid + i * 256;
            int dp  = idx >> 5;
            int b2  = (idx & 31) * 2;
            float2 ra = *(const float2*)(ut + (2 * dp) * BATCH + b2);
            float2 rb = *(const float2*)(ut + (2 * dp + 1) * BATCH + b2);
            *(uint2*)(uh + dp * USTR + b2) =
                make_uint2(packh2(ra.x, rb.x), packh2(ra.y, rb.y));
        }
    }
    ((uint4*)WINB)[tid]        = ((const uint4*)g_win_h)[tid];
    ((uint4*)WINB)[tid + 256]  = ((const uint4*)g_win_h)[tid + 256];
    ((uint4*)WOUTB)[tid]       = ((const uint4*)g_wout_h)[tid];
    ((uint4*)WOUTB)[tid + 256] = ((const uint4*)g_wout_h)[tid + 256];

    float C2a[4][4], C2b[4][4];
#pragma unroll
    for (int a = 0; a < 4; ++a)
#pragma unroll
        for (int q = 0; q < 4; ++q) { C2a[a][q] = 0.0f; C2b[a][q] = 0.0f; }

    int n0 = nb + w * 8 + 2 * qq;
    int nl = w * 8 + 2 * qq;
    int n  = w * 8 + rr;

    __syncthreads();

    for (int c = 0; c < NCHUNK; ++c) {
        // ---- prefetch base (shared by t0/t1) + noise[t0] ----
        float2 bs[8], nz[8];
#pragma unroll
        for (int mt = 0; mt < 4; ++mt)
#pragma unroll
            for (int hh = 0; hh < 2; ++hh) {
                int hg = c * HC + mt * 16 + hh * 8 + rr;
                bs[mt * 2 + hh] = *(const float2*)(g_base + (size_t)hg * BATCH + n0);
                nz[mt * 2 + hh] = *(const float2*)(noise + ((size_t)t0 * DH + hg) * BATCH + n0);
            }

        // ---- stage win[c+1] ----
        if (c + 1 < NCHUNK) {
            uint4* dst = (uint4*)(WINB + ((c + 1) & 1) * 2048);
            const uint4* src = ((const uint4*)g_win_h) + (size_t)(c + 1) * 512;
            dst[tid]       = src[tid];
            dst[tid + 256] = src[tid + 256];
        }

        // ---- GEMM1 both t: inp = win_h @ u_h (single pass) ----
        const unsigned* A1 = WINB + (c & 1) * 2048;
        const unsigned* uh0 = smu + OFF_UH0;
        const unsigned* uh1 = smu + OFF_UH1;
        float C1a[4][4], C1b[4][4];
#pragma unroll
        for (int a = 0; a < 4; ++a)
#pragma unroll
            for (int q = 0; q < 4; ++q) { C1a[a][q] = 0.0f; C1b[a][q] = 0.0f; }

#pragma unroll
        for (int kt = 0; kt < 4; ++kt) {
            int ra = (kt * 8 + qq) * USTR + n;
            int rb = (kt * 8 + 4 + qq) * USTR + n;
            unsigned ah0 = uh0[ra], ah1 = uh0[rb];
            unsigned bh0 = uh1[ra], bh1 = uh1[rb];
#pragma unroll
            for (int mt = 0; mt < 4; ++mt) {
                uint4 a4 = *(const uint4*)(A1 + ((kt * 4 + mt) * 32 + lane) * 4);
                mma_f16(C1a[mt][0], C1a[mt][1], C1a[mt][2], C1a[mt][3],
                        a4.x, a4.y, a4.z, a4.w, ah0, ah1);
                mma_f16(C1b[mt][0], C1b[mt][1], C1b[mt][2], C1b[mt][3],
                        a4.x, a4.y, a4.z, a4.w, bh0, bh1);
            }
        }

        // ---- epilogue t0: xs out + S (permuted pair layout, STS.64) ----
        unsigned* S0 = smu + OFF_S0 + (c & 1) * 2304;
#pragma unroll
        for (int mt = 0; mt < 4; ++mt) {
            int hg0 = c * HC + mt * 16 + rr;
            float2 nn0 = nz[mt * 2], nn1 = nz[mt * 2 + 1];
            float2 bb0 = bs[mt * 2], bb1 = bs[mt * 2 + 1];
            float xa0 = C1a[mt][0] + nn0.x + bb0.x;   // hh0 col0
            float xa1 = C1a[mt][1] + nn0.y + bb0.y;   // hh0 col1
            float xb0 = C1a[mt][2] + nn1.x + bb1.x;   // hh1 col0
            float xb1 = C1a[mt][3] + nn1.y + bb1.y;   // hh1 col1
            *(float2*)(xsout + ((size_t)t0 * DH + hg0) * BATCH + n0) = make_float2(xa0, xa1);
            *(float2*)(xsout + ((size_t)t0 * DH + hg0 + 8) * BATCH + n0) = make_float2(xb0, xb1);
            uint2 sw;
            sw.x = packh2(sigm(xa0), sigm(xb0));
            sw.y = packh2(sigm(xa1), sigm(xb1));
            *(uint2*)(S0 + (mt * 8 + rr) * USTR + nl) = sw;
        }

        // ---- prefetch noise[t1], epilogue t1 ----
#pragma unroll
        for (int mt = 0; mt < 4; ++mt)
#pragma unroll
            for (int hh = 0; hh < 2; ++hh) {
                int hg = c * HC + mt * 16 + hh * 8 + rr;
                nz[mt * 2 + hh] = *(const float2*)(noise + ((size_t)t1 * DH + hg) * BATCH + n0);
            }
        unsigned* S1 = smu + OFF_S1 + (c & 1) * 2304;
#pragma unroll
        for (int mt = 0; mt < 4; ++mt) {
            int hg0 = c * HC + mt * 16 + rr;
            float2 nn0 = nz[mt * 2], nn1 = nz[mt * 2 + 1];
            float2 bb0 = bs[mt * 2], bb1 = bs[mt * 2 + 1];
            float xa0 = C1b[mt][0] + nn0.x + bb0.x;
            float xa1 = C1b[mt][1] + nn0.y + bb0.y;
            float xb0 = C1b[mt][2] + nn1.x + bb1.x;
            float xb1 = C1b[mt][3] + nn1.y + bb1.y;
            *(float2*)(xsout + ((size_t)t1 * DH + hg0) * BATCH + n0) = make_float2(xa0, xa1);
            *(float2*)(xsout + ((size_t)t1 * DH + hg0 + 8) * BATCH + n0) = make_float2(xb0, xb1);
            uint2 sw;
            sw.x = packh2(sigm(xa0), sigm(xb0));
            sw.y = packh2(sigm(xa1), sigm(xb1));
            *(uint2*)(S1 + (mt * 8 + rr) * USTR + nl) = sw;
        }
        __syncthreads();   // the one sync per chunk

        // ---- stage wout[c+1] ----
        if (c + 1 < NCHUNK) {
            uint4* dst = (uint4*)(WOUTB + ((c + 1) & 1) * 2048);
            const uint4* src = ((const uint4*)g_wout_h) + (size_t)(c + 1) * 512;
            dst[tid]       = src[tid];
            dst[tid + 256] = src[tid + 256];
        }

        // ---- GEMM2 both t: out += wout_h @ s (permuted K) ----
        const unsigned* A2  = WOUTB + (c & 1) * 2048;
        const unsigned* S0r = smu + OFF_S0 + (c & 1) * 2304;
        const unsigned* S1r = smu + OFF_S1 + (c & 1) * 2304;
#pragma unroll
        for (int kt = 0; kt < 4; ++kt) {
            int ra = (kt * 8 + qq) * USTR + n;
            int rb = (kt * 8 + 4 + qq) * USTR + n;
            unsigned sa0 = S0r[ra], sa1 = S0r[rb];
            unsigned sb0 = S1r[ra], sb1 = S1r[rb];
#pragma unroll
            for (int mt = 0; mt < 4; ++mt) {
                uint4 a4 = *(const uint4*)(A2 + ((kt * 4 + mt) * 32 + lane) * 4);
                mma_f16(C2a[mt][0], C2a[mt][1], C2a[mt][2], C2a[mt][3],
                        a4.x, a4.y, a4.z, a4.w, sa0, sa1);
                mma_f16(C2b[mt][0], C2b[mt][1], C2b[mt][2], C2b[mt][3],
                        a4.x, a4.y, a4.z, a4.w, sb0, sb1);
            }
        }
    }

    // ---- write outputs[t0], outputs[t1] ----
#pragma unroll
    for (int mt = 0; mt < 4; ++mt) {
        int o0 = mt * 16 + rr;
        float bv0 = __ldg(bias + o0);
        float bv8 = __ldg(bias + o0 + 8);
        *(float2*)(out + ((size_t)t0 * DO + o0) * BATCH + n0) =
            make_float2(C2a[mt][0] + bv0, C2a[mt][1] + bv0);
        *(float2*)(out + ((size_t)t0 * DO + o0 + 8) * BATCH + n0) =
            make_float2(C2a[mt][2] + bv8, C2a[mt][3] + bv8);
        *(float2*)(out + ((size_t)t1 * DO + o0) * BATCH + n0) =
            make_float2(C2b[mt][0] + bv0, C2b[mt][1] + bv0);
        *(float2*)(out + ((size_t)t1 * DO + o0 + 8) * BATCH + n0) =
            make_float2(C2b[mt][2] + bv8, C2b[mt][3] + bv8);
    }
}

extern "C" void kernel_launch(void* const* d_in, const int* in_sizes, int n_in,
                              void* d_out, int out_size) {
    const float* u     = (const float*)d_in[0];
    const float* r0    = (const float*)d_in[1];
    const float* noise = (const float*)d_in[2];
    const float* win   = (const float*)d_in[3];
    const float* w_    = (const float*)d_in[4];
    // d_in[5] = m_diag: unused — |_w * (+-1)| == |_w|
    const float* wout  = (const float*)d_in[6];
    const float* bias  = (const float*)d_in[7];
    const float* taus  = (const float*)d_in[8];
    float* out = (float*)d_out;

    const int main_smem = SMEM_U32 * 4;   // 88064 B -> 2 blocks/SM
    cudaFuncSetAttribute(main_kernel, cudaFuncAttributeMaxDynamicSharedMemorySize, main_smem);

    pack_all_kernel<<<2432, 256>>>(win, wout, r0, w_);
    base_gemm_kernel<<<256, 256>>>();
    base_reduce_kernel<<<256, 256>>>(r0, taus);
    main_kernel<<<T_STEPS, 256, main_smem>>>(u, noise, bias, out);
}